// round 2
// baseline (speedup 1.0000x reference)
#include <cuda_runtime.h>
#include <math.h>

// Problem constants
#define NB    8192
#define NS    128
#define NT    64
#define NOBS  64
#define NLAT  128
#define NENC  256
#define NODE  256
#define NDEC  256
#define NSUB  4

#define TM       64    // batch rows per CTA
#define NTHREADS 256   // 8 warps: ty = warp id (8 rows each), tx = lane (cols)

// Ping-pong state buffers (static device scratch -- allocation-free rule)
static __device__ float g_h[2][NB * NENC];  // RNN hidden
static __device__ float g_z[2][NB * NLAT];  // latent state

__device__ __forceinline__ float f4c(const float4 v, int k) {
    return k == 0 ? v.x : k == 1 ? v.y : k == 2 ? v.z : v.w;
}

// Register-tiled GEMM fragment: C[64 x 32*CPT] += A(smem)[64 x K] * B(global)[K x ldb-slice]
// Thread (ty,tx): rows ty*8..ty*8+7, cols tx*CPT..tx*CPT+CPT-1.
// A reads are warp-uniform (broadcast LDS.128); B reads are coalesced LDG.128 rows,
// identical across the 8 warps -> L1 hits. Weights are tiny and L2-resident.
template<int CPT>
__device__ __forceinline__ void gemm_acc(
    const float* __restrict__ As, int lda, int K,
    const float* __restrict__ Bg, int ldb,
    int tx, int ty, float (&acc)[8][CPT])
{
    const float* Brow = Bg + tx * CPT;
    #pragma unroll 1
    for (int k4 = 0; k4 < (K >> 2); ++k4) {
        float4 av[8];
        #pragma unroll
        for (int i = 0; i < 8; ++i)
            av[i] = *reinterpret_cast<const float4*>(&As[(ty * 8 + i) * lda + (k4 << 2)]);
        #pragma unroll
        for (int kk = 0; kk < 4; ++kk) {
            const float* bp = Brow + (k4 * 4 + kk) * ldb;
            float b[CPT];
            if constexpr (CPT == 8) {
                float4 b0 = __ldg(reinterpret_cast<const float4*>(bp));
                float4 b1 = __ldg(reinterpret_cast<const float4*>(bp) + 1);
                b[0]=b0.x; b[1]=b0.y; b[2]=b0.z; b[3]=b0.w;
                b[4]=b1.x; b[5]=b1.y; b[6]=b1.z; b[7]=b1.w;
            } else if constexpr (CPT == 4) {
                float4 b0 = __ldg(reinterpret_cast<const float4*>(bp));
                b[0]=b0.x; b[1]=b0.y; b[2]=b0.z; b[3]=b0.w;
            } else {
                float2 b0 = __ldg(reinterpret_cast<const float2*>(bp));
                b[0]=b0.x; b[1]=b0.y;
            }
            #pragma unroll
            for (int i = 0; i < 8; ++i) {
                float a = f4c(av[i], kk);
                #pragma unroll
                for (int j = 0; j < CPT; ++j)
                    acc[i][j] = fmaf(a, b[j], acc[i][j]);
            }
        }
    }
}

// -------------------- RNN step: h' = tanh([x_t, h] @ Wi2h + b) --------------------
__global__ void __launch_bounds__(NTHREADS)
rnn_step_kernel(const float* __restrict__ obs,
                const float* __restrict__ Wi2h,
                const float* __restrict__ bi2h,
                int t, int in_sel, int out_sel, int first)
{
    extern __shared__ float sm[];                 // A tile [64][320]
    const int KA = NOBS + NENC;                   // 320
    int tid = threadIdx.x, tx = tid & 31, ty = tid >> 5;
    int m0 = blockIdx.x * TM;

    // stage X part (cols 0..63)
    const float* xsrc = obs + ((size_t)m0 * NS + t) * NOBS;
    for (int i = tid * 4; i < TM * NOBS; i += NTHREADS * 4) {
        int m = i >> 6, k = i & (NOBS - 1);
        *reinterpret_cast<float4*>(&sm[m * KA + k]) =
            __ldg(reinterpret_cast<const float4*>(&xsrc[(size_t)m * NS * NOBS + k]));
    }
    // stage H part (cols 64..319)
    if (!first) {
        const float* hsrc = g_h[in_sel] + (size_t)m0 * NENC;
        for (int i = tid * 4; i < TM * NENC; i += NTHREADS * 4) {
            int m = i >> 8, k = i & (NENC - 1);
            *reinterpret_cast<float4*>(&sm[m * KA + NOBS + k]) =
                *reinterpret_cast<const float4*>(&hsrc[m * NENC + k]);
        }
    }
    __syncthreads();

    float acc[8][8];
    #pragma unroll
    for (int i = 0; i < 8; ++i)
        #pragma unroll
        for (int j = 0; j < 8; ++j) acc[i][j] = 0.f;

    gemm_acc<8>(sm, KA, first ? NOBS : KA, Wi2h, NENC, tx, ty, acc);

    float bv[8];
    {
        float4 b0 = __ldg(reinterpret_cast<const float4*>(bi2h + tx * 8));
        float4 b1 = __ldg(reinterpret_cast<const float4*>(bi2h + tx * 8) + 1);
        bv[0]=b0.x; bv[1]=b0.y; bv[2]=b0.z; bv[3]=b0.w;
        bv[4]=b1.x; bv[5]=b1.y; bv[6]=b1.z; bv[7]=b1.w;
    }
    float* hdst = g_h[out_sel] + (size_t)m0 * NENC + tx * 8;
    #pragma unroll
    for (int i = 0; i < 8; ++i) {
        int row = ty * 8 + i;
        float4 v0, v1;
        v0.x = tanhf(acc[i][0] + bv[0]); v0.y = tanhf(acc[i][1] + bv[1]);
        v0.z = tanhf(acc[i][2] + bv[2]); v0.w = tanhf(acc[i][3] + bv[3]);
        v1.x = tanhf(acc[i][4] + bv[4]); v1.y = tanhf(acc[i][5] + bv[5]);
        v1.z = tanhf(acc[i][6] + bv[6]); v1.w = tanhf(acc[i][7] + bv[7]);
        *reinterpret_cast<float4*>(&hdst[row * NENC])     = v0;
        *reinterpret_cast<float4*>(&hdst[row * NENC + 4]) = v1;
    }
}

// -------------------- Encoder head: mean/logvar/z0 --------------------
__global__ void __launch_bounds__(NTHREADS)
head_kernel(const float* __restrict__ Wh2o, const float* __restrict__ bh2o,
            const float* __restrict__ eps, float* __restrict__ out, int hin_sel)
{
    extern __shared__ float sm[];                 // reused: A tile then out tile [64][256]
    int tid = threadIdx.x, tx = tid & 31, ty = tid >> 5;
    int m0 = blockIdx.x * TM;

    const float* hsrc = g_h[hin_sel] + (size_t)m0 * NENC;
    for (int i = tid * 4; i < TM * NENC; i += NTHREADS * 4)
        *reinterpret_cast<float4*>(&sm[i]) =
            *reinterpret_cast<const float4*>(&hsrc[i]);
    __syncthreads();

    float acc[8][8];
    #pragma unroll
    for (int i = 0; i < 8; ++i)
        #pragma unroll
        for (int j = 0; j < 8; ++j) acc[i][j] = 0.f;
    gemm_acc<8>(sm, NENC, NENC, Wh2o, 2 * NLAT, tx, ty, acc);

    float bv[8];
    {
        float4 b0 = __ldg(reinterpret_cast<const float4*>(bh2o + tx * 8));
        float4 b1 = __ldg(reinterpret_cast<const float4*>(bh2o + tx * 8) + 1);
        bv[0]=b0.x; bv[1]=b0.y; bv[2]=b0.z; bv[3]=b0.w;
        bv[4]=b1.x; bv[5]=b1.y; bv[6]=b1.z; bv[7]=b1.w;
    }
    __syncthreads();   // all threads done reading A tile
    #pragma unroll
    for (int i = 0; i < 8; ++i) {
        int row = ty * 8 + i;
        #pragma unroll
        for (int j = 0; j < 8; ++j)
            sm[row * (2 * NLAT) + tx * 8 + j] = acc[i][j] + bv[j];
    }
    __syncthreads();

    const size_t MEAN_OFF = (size_t)NT * NB * NOBS;
    const size_t LV_OFF   = MEAN_OFF + (size_t)NB * NLAT;
    for (int i = tid; i < TM * NLAT; i += NTHREADS) {
        int m = i >> 7, l = i & (NLAT - 1);
        float mean = sm[m * (2 * NLAT) + l];
        float lv   = sm[m * (2 * NLAT) + NLAT + l];
        float z0   = mean + __ldg(&eps[(size_t)(m0 + m) * NLAT + l]) * expf(0.5f * lv);
        g_z[0][(size_t)(m0 + m) * NLAT + l] = z0;
        out[MEAN_OFF + (size_t)(m0 + m) * NLAT + l] = mean;
        out[LV_OFF   + (size_t)(m0 + m) * NLAT + l] = lv;
    }
}

// -------------------- One fused RK4 substep: 4 stages of f(z)=tanh(zW1+b1)W2+b2 --------------------
__global__ void __launch_bounds__(NTHREADS)
ode_substep_kernel(const float* __restrict__ W1, const float* __restrict__ b1,
                   const float* __restrict__ W2, const float* __restrict__ b2,
                   const float* __restrict__ ptimes, int interval, int zin_sel)
{
    extern __shared__ float sm[];
    float* z0_s = sm;                        // [64][128]
    float* zc_s = sm + TM * NLAT;            // [64][128]
    float* g_s  = sm + 2 * TM * NLAT;        // [64][256]
    int tid = threadIdx.x, tx = tid & 31, ty = tid >> 5;
    int m0 = blockIdx.x * TM;

    float dt = (__ldg(&ptimes[interval + 1]) - __ldg(&ptimes[interval])) / (float)NSUB;

    const float* zsrc = g_z[zin_sel] + (size_t)m0 * NLAT;
    for (int i = tid * 4; i < TM * NLAT; i += NTHREADS * 4) {
        float4 v = *reinterpret_cast<const float4*>(&zsrc[i]);
        *reinterpret_cast<float4*>(&z0_s[i]) = v;
        *reinterpret_cast<float4*>(&zc_s[i]) = v;
    }
    __syncthreads();

    float b1v[8], b2v[4];
    {
        float4 a0 = __ldg(reinterpret_cast<const float4*>(b1 + tx * 8));
        float4 a1 = __ldg(reinterpret_cast<const float4*>(b1 + tx * 8) + 1);
        b1v[0]=a0.x; b1v[1]=a0.y; b1v[2]=a0.z; b1v[3]=a0.w;
        b1v[4]=a1.x; b1v[5]=a1.y; b1v[6]=a1.z; b1v[7]=a1.w;
        float4 c0 = __ldg(reinterpret_cast<const float4*>(b2 + tx * 4));
        b2v[0]=c0.x; b2v[1]=c0.y; b2v[2]=c0.z; b2v[3]=c0.w;
    }

    float zacc[8][4];   // RK4 accumulator z + dt/6*(k1+2k2+2k3+k4), in registers
    #pragma unroll
    for (int i = 0; i < 8; ++i) {
        float4 v = *reinterpret_cast<const float4*>(&z0_s[(ty * 8 + i) * NLAT + tx * 4]);
        zacc[i][0]=v.x; zacc[i][1]=v.y; zacc[i][2]=v.z; zacc[i][3]=v.w;
    }

    const float wts[4] = {dt / 6.f, dt / 3.f, dt / 3.f, dt / 6.f};
    const float cin[4] = {0.5f * dt, 0.5f * dt, dt, 0.f};

    #pragma unroll 1
    for (int s = 0; s < 4; ++s) {
        // g = tanh(zc @ W1 + b1)
        float acc1[8][8];
        #pragma unroll
        for (int i = 0; i < 8; ++i)
            #pragma unroll
            for (int j = 0; j < 8; ++j) acc1[i][j] = 0.f;
        gemm_acc<8>(zc_s, NLAT, NLAT, W1, NODE, tx, ty, acc1);
        #pragma unroll
        for (int i = 0; i < 8; ++i) {
            int row = ty * 8 + i;
            float4 v0, v1;
            v0.x = tanhf(acc1[i][0] + b1v[0]); v0.y = tanhf(acc1[i][1] + b1v[1]);
            v0.z = tanhf(acc1[i][2] + b1v[2]); v0.w = tanhf(acc1[i][3] + b1v[3]);
            v1.x = tanhf(acc1[i][4] + b1v[4]); v1.y = tanhf(acc1[i][5] + b1v[5]);
            v1.z = tanhf(acc1[i][6] + b1v[6]); v1.w = tanhf(acc1[i][7] + b1v[7]);
            *reinterpret_cast<float4*>(&g_s[row * NODE + tx * 8])     = v0;
            *reinterpret_cast<float4*>(&g_s[row * NODE + tx * 8 + 4]) = v1;
        }
        __syncthreads();
        // k = g @ W2 + b2 ; fold into accumulator and next zc
        float acc2[8][4];
        #pragma unroll
        for (int i = 0; i < 8; ++i)
            #pragma unroll
            for (int j = 0; j < 4; ++j) acc2[i][j] = 0.f;
        gemm_acc<4>(g_s, NODE, NODE, W2, NLAT, tx, ty, acc2);
        #pragma unroll
        for (int i = 0; i < 8; ++i) {
            int row = ty * 8 + i;
            #pragma unroll
            for (int j = 0; j < 4; ++j) {
                float kv = acc2[i][j] + b2v[j];
                zacc[i][j] += wts[s] * kv;
                if (s < 3)
                    zc_s[row * NLAT + tx * 4 + j] =
                        z0_s[row * NLAT + tx * 4 + j] + cin[s] * kv;
            }
        }
        __syncthreads();
    }

    float* zdst = g_z[1 - zin_sel] + (size_t)m0 * NLAT;
    #pragma unroll
    for (int i = 0; i < 8; ++i) {
        int row = ty * 8 + i;
        float4 v = make_float4(zacc[i][0], zacc[i][1], zacc[i][2], zacc[i][3]);
        *reinterpret_cast<float4*>(&zdst[row * NLAT + tx * 4]) = v;
    }
}

// -------------------- Decoder: o = relu(z@Wd1+b1)@Wd2+b2 for one time index --------------------
__global__ void __launch_bounds__(NTHREADS)
decode_kernel(const float* __restrict__ W1, const float* __restrict__ b1,
              const float* __restrict__ W2, const float* __restrict__ b2,
              float* __restrict__ out, int tindex)
{
    extern __shared__ float sm[];
    float* z_s = sm;                    // [64][128]
    float* g_s = sm + TM * NLAT;        // [64][256]
    int tid = threadIdx.x, tx = tid & 31, ty = tid >> 5;
    int m0 = blockIdx.x * TM;

    const float* zsrc = g_z[0] + (size_t)m0 * NLAT;
    for (int i = tid * 4; i < TM * NLAT; i += NTHREADS * 4)
        *reinterpret_cast<float4*>(&z_s[i]) =
            *reinterpret_cast<const float4*>(&zsrc[i]);
    __syncthreads();

    float acc1[8][8];
    #pragma unroll
    for (int i = 0; i < 8; ++i)
        #pragma unroll
        for (int j = 0; j < 8; ++j) acc1[i][j] = 0.f;
    gemm_acc<8>(z_s, NLAT, NLAT, W1, NDEC, tx, ty, acc1);

    float b1v[8];
    {
        float4 a0 = __ldg(reinterpret_cast<const float4*>(b1 + tx * 8));
        float4 a1 = __ldg(reinterpret_cast<const float4*>(b1 + tx * 8) + 1);
        b1v[0]=a0.x; b1v[1]=a0.y; b1v[2]=a0.z; b1v[3]=a0.w;
        b1v[4]=a1.x; b1v[5]=a1.y; b1v[6]=a1.z; b1v[7]=a1.w;
    }
    #pragma unroll
    for (int i = 0; i < 8; ++i) {
        int row = ty * 8 + i;
        float4 v0, v1;
        v0.x = fmaxf(acc1[i][0] + b1v[0], 0.f); v0.y = fmaxf(acc1[i][1] + b1v[1], 0.f);
        v0.z = fmaxf(acc1[i][2] + b1v[2], 0.f); v0.w = fmaxf(acc1[i][3] + b1v[3], 0.f);
        v1.x = fmaxf(acc1[i][4] + b1v[4], 0.f); v1.y = fmaxf(acc1[i][5] + b1v[5], 0.f);
        v1.z = fmaxf(acc1[i][6] + b1v[6], 0.f); v1.w = fmaxf(acc1[i][7] + b1v[7], 0.f);
        *reinterpret_cast<float4*>(&g_s[row * NDEC + tx * 8])     = v0;
        *reinterpret_cast<float4*>(&g_s[row * NDEC + tx * 8 + 4]) = v1;
    }
    __syncthreads();

    float acc2[8][2];
    #pragma unroll
    for (int i = 0; i < 8; ++i) { acc2[i][0] = 0.f; acc2[i][1] = 0.f; }
    gemm_acc<2>(g_s, NDEC, NDEC, W2, NOBS, tx, ty, acc2);

    float2 b2v = __ldg(reinterpret_cast<const float2*>(b2 + tx * 2));
    float* od = out + (size_t)tindex * NB * NOBS + (size_t)m0 * NOBS + tx * 2;
    #pragma unroll
    for (int i = 0; i < 8; ++i) {
        int row = ty * 8 + i;
        float2 v = make_float2(acc2[i][0] + b2v.x, acc2[i][1] + b2v.y);
        *reinterpret_cast<float2*>(&od[row * NOBS]) = v;
    }
}

// -------------------- Launcher --------------------
extern "C" void kernel_launch(void* const* d_in, const int* in_sizes, int n_in,
                              void* d_out, int out_size)
{
    const float* obs    = (const float*)d_in[0];
    /* d_in[1] observed_times: unused by the reference computation */
    const float* ptimes = (const float*)d_in[2];
    const float* eps    = (const float*)d_in[3];
    const float* Wi2h   = (const float*)d_in[4];
    const float* bi2h   = (const float*)d_in[5];
    const float* Wh2o   = (const float*)d_in[6];
    const float* bh2o   = (const float*)d_in[7];
    const float* Wode1  = (const float*)d_in[8];
    const float* bode1  = (const float*)d_in[9];
    const float* Wode2  = (const float*)d_in[10];
    const float* bode2  = (const float*)d_in[11];
    const float* Wdec1  = (const float*)d_in[12];
    const float* bdec1  = (const float*)d_in[13];
    const float* Wdec2  = (const float*)d_in[14];
    const float* bdec2  = (const float*)d_in[15];
    float* out = (float*)d_out;

    const int SM_RNN  = TM * (NOBS + NENC) * 4;          // 81920
    const int SM_HEAD = TM * NENC * 4;                   // 65536
    const int SM_ODE  = (2 * TM * NLAT + TM * NODE) * 4; // 131072
    const int SM_DEC  = (TM * NLAT + TM * NDEC) * 4;     // 98304

    cudaFuncSetAttribute(rnn_step_kernel,    cudaFuncAttributeMaxDynamicSharedMemorySize, SM_RNN);
    cudaFuncSetAttribute(head_kernel,        cudaFuncAttributeMaxDynamicSharedMemorySize, SM_HEAD);
    cudaFuncSetAttribute(ode_substep_kernel, cudaFuncAttributeMaxDynamicSharedMemorySize, SM_ODE);
    cudaFuncSetAttribute(decode_kernel,      cudaFuncAttributeMaxDynamicSharedMemorySize, SM_DEC);

    dim3 grid(NB / TM);   // 128 CTAs

    // RNN over reversed sequence. step s: out buffer = s&1 flipped so h_final lands in g_h[1].
    for (int s = 0; s < NS; ++s) {
        int t = NS - 1 - s;
        rnn_step_kernel<<<grid, NTHREADS, SM_RNN>>>(obs, Wi2h, bi2h, t,
                                                    1 - (s & 1), s & 1, s == 0);
    }
    head_kernel<<<grid, NTHREADS, SM_HEAD>>>(Wh2o, bh2o, eps, out, (NS - 1) & 1);

    decode_kernel<<<grid, NTHREADS, SM_DEC>>>(Wdec1, bdec1, Wdec2, bdec2, out, 0);
    for (int iv = 0; iv < NT - 1; ++iv) {
        for (int ss = 0; ss < NSUB; ++ss)
            ode_substep_kernel<<<grid, NTHREADS, SM_ODE>>>(Wode1, bode1, Wode2, bode2,
                                                           ptimes, iv, ss & 1);
        // 4 substeps flip the ping-pong twice -> result is back in g_z[0]
        decode_kernel<<<grid, NTHREADS, SM_DEC>>>(Wdec1, bdec1, Wdec2, bdec2, out, iv + 1);
    }
}

// round 3
// speedup vs baseline: 1.3758x; 1.3758x over previous
#include <cuda_runtime.h>
#include <math.h>

// Problem constants
#define NB    8192
#define NS    128
#define NT    64
#define NOBS  64
#define NLAT  128
#define NENC  256
#define NODE  256
#define NDEC  256
#define NSUB  4

#define TM       64    // batch rows per CTA
#define NTHREADS 256   // 8 warps, each warp owns 8 rows -- warps fully independent

typedef unsigned long long u64;

// z0 handoff between the two persistent kernels (static scratch: allocation-free rule)
static __device__ float g_z0[NB * NLAT];

__device__ __forceinline__ u64 pk2(float x, float y) {
    u64 r; asm("mov.b64 %0, {%1, %2};" : "=l"(r) : "f"(x), "f"(y)); return r;
}
__device__ __forceinline__ void upk2(float& x, float& y, u64 v) {
    asm("mov.b64 {%0, %1}, %2;" : "=f"(x), "=f"(y) : "l"(v));
}
// packed fp32x2 FMA: d = a*b + d (elementwise on two f32 lanes) -> SASS FFMA2, 2x fp32 rate
__device__ __forceinline__ void ffma2(u64& d, u64 a, u64 b) {
    asm("fma.rn.f32x2 %0, %1, %2, %0;" : "+l"(d) : "l"(a), "l"(b));
}
__device__ __forceinline__ float f4c(const float4 v, int k) {
    return k == 0 ? v.x : k == 1 ? v.y : k == 2 ? v.z : v.w;
}

// Warp-local register-tiled GEMM with packed FFMA2.
// C[8 rows x 32*CPT cols] += A(smem, rows row0..row0+7)[8 x K] * B(global)[K x ldb slice].
// acc[i][j] is a packed pair of columns (tx*CPT + 2j, +2j+1).
// A reads are warp-broadcast LDS.128; B reads are coalesced 16B LDG (L1/L2-resident weights).
template<int CPT>
__device__ __forceinline__ void wgemm(
    const float* __restrict__ As, int lda, int K,
    const float* __restrict__ Bg, int ldb,
    int tx, int row0, u64 (&acc)[8][CPT / 2])
{
    const float* Brow = Bg + tx * CPT;
    #pragma unroll 2
    for (int k4 = 0; k4 < (K >> 2); ++k4) {
        float4 av[8];
        #pragma unroll
        for (int i = 0; i < 8; ++i)
            av[i] = *reinterpret_cast<const float4*>(&As[(row0 + i) * lda + (k4 << 2)]);
        #pragma unroll
        for (int kk = 0; kk < 4; ++kk) {
            const float* bp = Brow + (k4 * 4 + kk) * ldb;
            u64 bq[CPT / 2];
            if constexpr (CPT == 8) {
                ulonglong2 q0 = __ldg(reinterpret_cast<const ulonglong2*>(bp));
                ulonglong2 q1 = __ldg(reinterpret_cast<const ulonglong2*>(bp) + 1);
                bq[0] = q0.x; bq[1] = q0.y; bq[2] = q1.x; bq[3] = q1.y;
            } else if constexpr (CPT == 4) {
                ulonglong2 q0 = __ldg(reinterpret_cast<const ulonglong2*>(bp));
                bq[0] = q0.x; bq[1] = q0.y;
            } else {
                bq[0] = __ldg(reinterpret_cast<const u64*>(bp));
            }
            #pragma unroll
            for (int i = 0; i < 8; ++i) {
                float a = f4c(av[i], kk);
                u64 aa = pk2(a, a);
                #pragma unroll
                for (int j = 0; j < CPT / 2; ++j) ffma2(acc[i][j], aa, bq[j]);
            }
        }
    }
}

// ==================== Persistent encoder: 128 RNN steps + head, one launch ====================
__global__ void __launch_bounds__(NTHREADS)
encoder_kernel(const float* __restrict__ obs,
               const float* __restrict__ Wi2h, const float* __restrict__ bi2h,
               const float* __restrict__ Wh2o, const float* __restrict__ bh2o,
               const float* __restrict__ eps, float* __restrict__ out)
{
    extern __shared__ float A[];                 // [64][320]: [x(64) | h(256)] per row
    const int lda = NOBS + NENC;                 // 320
    int tid = threadIdx.x, tx = tid & 31, ty = tid >> 5, row0 = ty * 8;
    int m0 = blockIdx.x * TM;

    // zero the h region of this warp's rows
    #pragma unroll
    for (int i = 0; i < 8; ++i) {
        *reinterpret_cast<float4*>(&A[(row0 + i) * lda + NOBS + tx * 4])       = make_float4(0, 0, 0, 0);
        *reinterpret_cast<float4*>(&A[(row0 + i) * lda + NOBS + 128 + tx * 4]) = make_float4(0, 0, 0, 0);
    }
    float bv[8];
    {
        float4 b0 = __ldg(reinterpret_cast<const float4*>(bi2h + tx * 8));
        float4 b1 = __ldg(reinterpret_cast<const float4*>(bi2h + tx * 8) + 1);
        bv[0]=b0.x; bv[1]=b0.y; bv[2]=b0.z; bv[3]=b0.w;
        bv[4]=b1.x; bv[5]=b1.y; bv[6]=b1.z; bv[7]=b1.w;
    }
    __syncwarp();

    #pragma unroll 1
    for (int s = 0; s < NS; ++s) {
        int t = NS - 1 - s;
        // load x_t for this warp's 8 rows (8 rows x 16 float4, coalesced)
        #pragma unroll
        for (int p = 0; p < 4; ++p) {
            int r = p * 2 + (tx >> 4), f = tx & 15;
            *reinterpret_cast<float4*>(&A[(row0 + r) * lda + f * 4]) =
                __ldg(reinterpret_cast<const float4*>(
                    &obs[((size_t)(m0 + row0 + r) * NS + t) * NOBS + f * 4]));
        }
        __syncwarp();
        u64 acc[8][4];
        #pragma unroll
        for (int i = 0; i < 8; ++i) { acc[i][0]=0; acc[i][1]=0; acc[i][2]=0; acc[i][3]=0; }
        wgemm<8>(A, lda, lda, Wi2h, NENC, tx, row0, acc);
        __syncwarp();
        #pragma unroll
        for (int i = 0; i < 8; ++i) {
            float c0,c1,c2,c3,c4,c5,c6,c7;
            upk2(c0,c1,acc[i][0]); upk2(c2,c3,acc[i][1]);
            upk2(c4,c5,acc[i][2]); upk2(c6,c7,acc[i][3]);
            float4 v0 = make_float4(tanhf(c0+bv[0]), tanhf(c1+bv[1]), tanhf(c2+bv[2]), tanhf(c3+bv[3]));
            float4 v1 = make_float4(tanhf(c4+bv[4]), tanhf(c5+bv[5]), tanhf(c6+bv[6]), tanhf(c7+bv[7]));
            *reinterpret_cast<float4*>(&A[(row0 + i) * lda + NOBS + tx * 8])     = v0;
            *reinterpret_cast<float4*>(&A[(row0 + i) * lda + NOBS + tx * 8 + 4]) = v1;
        }
        __syncwarp();
    }

    // head: o = h @ Wh2o + bh2o  (h = A cols 64..319)
    u64 acc[8][4];
    #pragma unroll
    for (int i = 0; i < 8; ++i) { acc[i][0]=0; acc[i][1]=0; acc[i][2]=0; acc[i][3]=0; }
    wgemm<8>(A + NOBS, lda, NENC, Wh2o, 2 * NLAT, tx, row0, acc);
    float hb[8];
    {
        float4 b0 = __ldg(reinterpret_cast<const float4*>(bh2o + tx * 8));
        float4 b1 = __ldg(reinterpret_cast<const float4*>(bh2o + tx * 8) + 1);
        hb[0]=b0.x; hb[1]=b0.y; hb[2]=b0.z; hb[3]=b0.w;
        hb[4]=b1.x; hb[5]=b1.y; hb[6]=b1.z; hb[7]=b1.w;
    }
    __syncwarp();   // all lanes done reading h before overwriting the row
    #pragma unroll
    for (int i = 0; i < 8; ++i) {
        float c0,c1,c2,c3,c4,c5,c6,c7;
        upk2(c0,c1,acc[i][0]); upk2(c2,c3,acc[i][1]);
        upk2(c4,c5,acc[i][2]); upk2(c6,c7,acc[i][3]);
        float4 v0 = make_float4(c0+hb[0], c1+hb[1], c2+hb[2], c3+hb[3]);
        float4 v1 = make_float4(c4+hb[4], c5+hb[5], c6+hb[6], c7+hb[7]);
        *reinterpret_cast<float4*>(&A[(row0 + i) * lda + tx * 8])     = v0;  // out row [0..255]
        *reinterpret_cast<float4*>(&A[(row0 + i) * lda + tx * 8 + 4]) = v1;
    }
    __syncwarp();

    const size_t MEAN_OFF = (size_t)NT * NB * NOBS;
    const size_t LV_OFF   = MEAN_OFF + (size_t)NB * NLAT;
    #pragma unroll
    for (int i = 0; i < 8; ++i) {
        int m = m0 + row0 + i;
        float4 mv = *reinterpret_cast<const float4*>(&A[(row0 + i) * lda + tx * 4]);
        float4 lv = *reinterpret_cast<const float4*>(&A[(row0 + i) * lda + NLAT + tx * 4]);
        float4 ev = __ldg(reinterpret_cast<const float4*>(&eps[(size_t)m * NLAT + tx * 4]));
        float4 z;
        z.x = mv.x + ev.x * expf(0.5f * lv.x);
        z.y = mv.y + ev.y * expf(0.5f * lv.y);
        z.z = mv.z + ev.z * expf(0.5f * lv.z);
        z.w = mv.w + ev.w * expf(0.5f * lv.w);
        *reinterpret_cast<float4*>(&g_z0[(size_t)m * NLAT + tx * 4]) = z;
        *reinterpret_cast<float4*>(&out[MEAN_OFF + (size_t)m * NLAT + tx * 4]) = mv;
        *reinterpret_cast<float4*>(&out[LV_OFF   + (size_t)m * NLAT + tx * 4]) = lv;
    }
}

// ==================== Persistent ODE: 63 intervals x 4 RK4 substeps + 64 decodes ====================
__global__ void __launch_bounds__(NTHREADS)
ode_kernel(const float* __restrict__ W1,  const float* __restrict__ b1,
           const float* __restrict__ W2,  const float* __restrict__ b2,
           const float* __restrict__ Wd1, const float* __restrict__ bd1,
           const float* __restrict__ Wd2, const float* __restrict__ bd2,
           const float* __restrict__ ptimes, float* __restrict__ out)
{
    extern __shared__ float sm[];
    float* Z = sm;                 // [64][128] current z / stage input
    float* G = sm + TM * NLAT;     // [64][256] hidden activations
    int tid = threadIdx.x, tx = tid & 31, ty = tid >> 5, row0 = ty * 8;
    int m0 = blockIdx.x * TM;

    float b1v[8], bd1v[8], b2v[4];
    float2 bd2v;
    {
        float4 a0 = __ldg(reinterpret_cast<const float4*>(b1 + tx * 8));
        float4 a1 = __ldg(reinterpret_cast<const float4*>(b1 + tx * 8) + 1);
        b1v[0]=a0.x; b1v[1]=a0.y; b1v[2]=a0.z; b1v[3]=a0.w;
        b1v[4]=a1.x; b1v[5]=a1.y; b1v[6]=a1.z; b1v[7]=a1.w;
        float4 d0 = __ldg(reinterpret_cast<const float4*>(bd1 + tx * 8));
        float4 d1 = __ldg(reinterpret_cast<const float4*>(bd1 + tx * 8) + 1);
        bd1v[0]=d0.x; bd1v[1]=d0.y; bd1v[2]=d0.z; bd1v[3]=d0.w;
        bd1v[4]=d1.x; bd1v[5]=d1.y; bd1v[6]=d1.z; bd1v[7]=d1.w;
        float4 c0 = __ldg(reinterpret_cast<const float4*>(b2 + tx * 4));
        b2v[0]=c0.x; b2v[1]=c0.y; b2v[2]=c0.z; b2v[3]=c0.w;
        bd2v = __ldg(reinterpret_cast<const float2*>(bd2 + tx * 2));
    }

    // current z in registers (this thread's 8 rows x 4 cols) + mirrored in Z smem
    float zr[8][4];
    #pragma unroll
    for (int i = 0; i < 8; ++i) {
        float4 v = *reinterpret_cast<const float4*>(&g_z0[(size_t)(m0 + row0 + i) * NLAT + tx * 4]);
        zr[i][0]=v.x; zr[i][1]=v.y; zr[i][2]=v.z; zr[i][3]=v.w;
        *reinterpret_cast<float4*>(&Z[(row0 + i) * NLAT + tx * 4]) = v;
    }
    __syncwarp();

    auto decode = [&](int tindex) {
        u64 a1[8][4];
        #pragma unroll
        for (int i = 0; i < 8; ++i) { a1[i][0]=0; a1[i][1]=0; a1[i][2]=0; a1[i][3]=0; }
        wgemm<8>(Z, NLAT, NLAT, Wd1, NDEC, tx, row0, a1);
        __syncwarp();
        #pragma unroll
        for (int i = 0; i < 8; ++i) {
            float c0,c1,c2,c3,c4,c5,c6,c7;
            upk2(c0,c1,a1[i][0]); upk2(c2,c3,a1[i][1]);
            upk2(c4,c5,a1[i][2]); upk2(c6,c7,a1[i][3]);
            float4 v0 = make_float4(fmaxf(c0+bd1v[0],0.f), fmaxf(c1+bd1v[1],0.f),
                                    fmaxf(c2+bd1v[2],0.f), fmaxf(c3+bd1v[3],0.f));
            float4 v1 = make_float4(fmaxf(c4+bd1v[4],0.f), fmaxf(c5+bd1v[5],0.f),
                                    fmaxf(c6+bd1v[6],0.f), fmaxf(c7+bd1v[7],0.f));
            *reinterpret_cast<float4*>(&G[(row0 + i) * NDEC + tx * 8])     = v0;
            *reinterpret_cast<float4*>(&G[(row0 + i) * NDEC + tx * 8 + 4]) = v1;
        }
        __syncwarp();
        u64 a2[8][1];
        #pragma unroll
        for (int i = 0; i < 8; ++i) a2[i][0] = 0;
        wgemm<2>(G, NDEC, NDEC, Wd2, NOBS, tx, row0, a2);
        #pragma unroll
        for (int i = 0; i < 8; ++i) {
            float x, y; upk2(x, y, a2[i][0]);
            *reinterpret_cast<float2*>(
                &out[(size_t)tindex * NB * NOBS + (size_t)(m0 + row0 + i) * NOBS + tx * 2]) =
                make_float2(x + bd2v.x, y + bd2v.y);
        }
        __syncwarp();
    };

    decode(0);

    #pragma unroll 1
    for (int iv = 0; iv < NT - 1; ++iv) {
        float dt = (__ldg(&ptimes[iv + 1]) - __ldg(&ptimes[iv])) * (1.0f / NSUB);
        #pragma unroll 1
        for (int ss = 0; ss < NSUB; ++ss) {
            float zb[8][4];   // RK4 base = z at substep start
            #pragma unroll
            for (int i = 0; i < 8; ++i)
                #pragma unroll
                for (int j = 0; j < 4; ++j) zb[i][j] = zr[i][j];

            #pragma unroll 1
            for (int s = 0; s < 4; ++s) {
                float wt = (s == 0 || s == 3) ? dt * (1.0f / 6.0f) : dt * (1.0f / 3.0f);
                float ci = (s == 2) ? dt : 0.5f * dt;

                // g = tanh(zc @ W1 + b1)
                u64 a1[8][4];
                #pragma unroll
                for (int i = 0; i < 8; ++i) { a1[i][0]=0; a1[i][1]=0; a1[i][2]=0; a1[i][3]=0; }
                wgemm<8>(Z, NLAT, NLAT, W1, NODE, tx, row0, a1);
                __syncwarp();
                #pragma unroll
                for (int i = 0; i < 8; ++i) {
                    float c0,c1,c2,c3,c4,c5,c6,c7;
                    upk2(c0,c1,a1[i][0]); upk2(c2,c3,a1[i][1]);
                    upk2(c4,c5,a1[i][2]); upk2(c6,c7,a1[i][3]);
                    float4 v0 = make_float4(tanhf(c0+b1v[0]), tanhf(c1+b1v[1]),
                                            tanhf(c2+b1v[2]), tanhf(c3+b1v[3]));
                    float4 v1 = make_float4(tanhf(c4+b1v[4]), tanhf(c5+b1v[5]),
                                            tanhf(c6+b1v[6]), tanhf(c7+b1v[7]));
                    *reinterpret_cast<float4*>(&G[(row0 + i) * NODE + tx * 8])     = v0;
                    *reinterpret_cast<float4*>(&G[(row0 + i) * NODE + tx * 8 + 4]) = v1;
                }
                __syncwarp();

                // k = g @ W2 + b2 ; fold into RK4 accumulator + next stage input
                u64 a2[8][2];
                #pragma unroll
                for (int i = 0; i < 8; ++i) { a2[i][0]=0; a2[i][1]=0; }
                wgemm<4>(G, NODE, NODE, W2, NLAT, tx, row0, a2);
                __syncwarp();   // all lanes done reading Z before rewriting it
                #pragma unroll
                for (int i = 0; i < 8; ++i) {
                    float k0,k1,k2,k3;
                    upk2(k0,k1,a2[i][0]); upk2(k2,k3,a2[i][1]);
                    k0 += b2v[0]; k1 += b2v[1]; k2 += b2v[2]; k3 += b2v[3];
                    zr[i][0] += wt * k0; zr[i][1] += wt * k1;
                    zr[i][2] += wt * k2; zr[i][3] += wt * k3;
                    float4 v;
                    if (s < 3)
                        v = make_float4(zb[i][0] + ci * k0, zb[i][1] + ci * k1,
                                        zb[i][2] + ci * k2, zb[i][3] + ci * k3);
                    else
                        v = make_float4(zr[i][0], zr[i][1], zr[i][2], zr[i][3]);
                    *reinterpret_cast<float4*>(&Z[(row0 + i) * NLAT + tx * 4]) = v;
                }
                __syncwarp();
            }
        }
        decode(iv + 1);
    }
}

// -------------------- Launcher --------------------
extern "C" void kernel_launch(void* const* d_in, const int* in_sizes, int n_in,
                              void* d_out, int out_size)
{
    const float* obs    = (const float*)d_in[0];
    /* d_in[1] observed_times: unused by the reference computation */
    const float* ptimes = (const float*)d_in[2];
    const float* eps    = (const float*)d_in[3];
    const float* Wi2h   = (const float*)d_in[4];
    const float* bi2h   = (const float*)d_in[5];
    const float* Wh2o   = (const float*)d_in[6];
    const float* bh2o   = (const float*)d_in[7];
    const float* Wode1  = (const float*)d_in[8];
    const float* bode1  = (const float*)d_in[9];
    const float* Wode2  = (const float*)d_in[10];
    const float* bode2  = (const float*)d_in[11];
    const float* Wdec1  = (const float*)d_in[12];
    const float* bdec1  = (const float*)d_in[13];
    const float* Wdec2  = (const float*)d_in[14];
    const float* bdec2  = (const float*)d_in[15];
    float* out = (float*)d_out;

    const int SM_ENC = TM * (NOBS + NENC) * 4;         // 81920
    const int SM_ODE = (TM * NLAT + TM * NODE) * 4;    // 98304

    cudaFuncSetAttribute(encoder_kernel, cudaFuncAttributeMaxDynamicSharedMemorySize, SM_ENC);
    cudaFuncSetAttribute(ode_kernel,     cudaFuncAttributeMaxDynamicSharedMemorySize, SM_ODE);

    dim3 grid(NB / TM);   // 128 CTAs

    encoder_kernel<<<grid, NTHREADS, SM_ENC>>>(obs, Wi2h, bi2h, Wh2o, bh2o, eps, out);
    ode_kernel<<<grid, NTHREADS, SM_ODE>>>(Wode1, bode1, Wode2, bode2,
                                           Wdec1, bdec1, Wdec2, bdec2, ptimes, out);
}

// round 4
// speedup vs baseline: 1.5066x; 1.0951x over previous
#include <cuda_runtime.h>
#include <math.h>

// Problem constants
#define NB    8192
#define NS    128
#define NT    64
#define NOBS  64
#define NLAT  128
#define NENC  256
#define NODE  256
#define NDEC  256
#define NSUB  4

#define TM       64     // batch rows per CTA
#define NTHREADS 512    // 16 warps; warps split the OUTPUT-COLUMN dimension

// padded leading dims: lda % 32 == 4 (floats) -> conflict-free strided-row LDS.128
#define LDA_Z 132
#define LDA_G 260
#define LDA_A 324

typedef unsigned long long u64;

static __device__ float g_z0[NB * NLAT];   // z0 handoff (static scratch)

__device__ __forceinline__ u64 pk2(float x, float y) {
    u64 r; asm("mov.b64 %0, {%1, %2};" : "=l"(r) : "f"(x), "f"(y)); return r;
}
__device__ __forceinline__ void upk2(float& x, float& y, u64 v) {
    asm("mov.b64 {%0, %1}, %2;" : "=f"(x), "=f"(y) : "l"(v));
}
// packed fp32x2 fma -> SASS FFMA2 (2x fp32 rate)
__device__ __forceinline__ void ffma2(u64& d, u64 a, u64 b) {
    asm("fma.rn.f32x2 %0, %1, %2, %0;" : "+l"(d) : "l"(a), "l"(b));
}
__device__ __forceinline__ float f4c(const float4 v, int k) {
    return k == 0 ? v.x : k == 1 ? v.y : k == 2 ? v.z : v.w;
}

// Split-N warp GEMM: this thread computes rows {rg+8i, i=0..7} x cols [col0, col0+2*PAIRS).
// A in smem (lda % 32 == 4 floats -> the 8 strided rows hit 8 distinct bank groups: conflict-free).
// B in global: lanes sharing cg read identical addresses (L1 broadcast); per warp only its own
// column slab is touched -> total B traffic per CTA per k = one copy of the B row.
template<int PAIRS>
__device__ __forceinline__ void wgemmN(
    const float* __restrict__ As, int lda, int K,
    const float* __restrict__ Bg, int ldb, int col0,
    int rg, u64 (&acc)[8][PAIRS])
{
    #pragma unroll 2
    for (int k4 = 0; k4 < (K >> 2); ++k4) {
        float4 av[8];
        #pragma unroll
        for (int i = 0; i < 8; ++i)
            av[i] = *reinterpret_cast<const float4*>(&As[(rg + 8 * i) * lda + (k4 << 2)]);
        #pragma unroll
        for (int kk = 0; kk < 4; ++kk) {
            const float* bp = Bg + (size_t)(k4 * 4 + kk) * ldb + col0;
            u64 bq[PAIRS];
            if constexpr (PAIRS == 2) {
                ulonglong2 q = __ldg(reinterpret_cast<const ulonglong2*>(bp));
                bq[0] = q.x; bq[1] = q.y;
            } else {
                bq[0] = __ldg(reinterpret_cast<const u64*>(bp));
            }
            #pragma unroll
            for (int i = 0; i < 8; ++i) {
                float a = f4c(av[i], kk);
                u64 aa = pk2(a, a);
                #pragma unroll
                for (int j = 0; j < PAIRS; ++j) ffma2(acc[i][j], aa, bq[j]);
            }
        }
    }
}

// scalar-column variant (decode output GEMM, 64 cols -> 1 col per lane)
__device__ __forceinline__ void wgemmS(
    const float* __restrict__ As, int lda, int K,
    const float* __restrict__ Bg, int ldb, int col0,
    int rg, float (&acc)[8])
{
    #pragma unroll 2
    for (int k4 = 0; k4 < (K >> 2); ++k4) {
        float4 av[8];
        #pragma unroll
        for (int i = 0; i < 8; ++i)
            av[i] = *reinterpret_cast<const float4*>(&As[(rg + 8 * i) * lda + (k4 << 2)]);
        #pragma unroll
        for (int kk = 0; kk < 4; ++kk) {
            float b = __ldg(&Bg[(size_t)(k4 * 4 + kk) * ldb + col0]);
            #pragma unroll
            for (int i = 0; i < 8; ++i)
                acc[i] = fmaf(f4c(av[i], kk), b, acc[i]);
        }
    }
}

// ==================== Persistent encoder: 128 RNN steps + head ====================
__global__ void __launch_bounds__(NTHREADS)
encoder_kernel(const float* __restrict__ obs,
               const float* __restrict__ Wi2h, const float* __restrict__ bi2h,
               const float* __restrict__ Wh2o, const float* __restrict__ bh2o,
               const float* __restrict__ eps, float* __restrict__ out)
{
    extern __shared__ float A[];                 // [64][324]: [x(64) | h(256) | pad(4)]
    int tid = threadIdx.x, lane = tid & 31, w = tid >> 5;
    int rg = lane >> 2, cg = lane & 3;
    int m0 = blockIdx.x * TM;
    int col1 = w * 16 + cg * 4;                  // 4-col slab in 256-col outputs

    // zero the h region
    for (int i = tid; i < TM * NENC / 4; i += NTHREADS) {
        int m = i >> 6, k = (i & 63) << 2;
        *reinterpret_cast<float4*>(&A[m * LDA_A + NOBS + k]) = make_float4(0, 0, 0, 0);
    }
    float4 bi = __ldg(reinterpret_cast<const float4*>(&bi2h[col1]));

    // load x for t = NS-1
    int xr = tid >> 3, xf = tid & 7;
    {
        const float* xp = &obs[((size_t)(m0 + xr) * NS + (NS - 1)) * NOBS + xf * 8];
        *reinterpret_cast<float4*>(&A[xr * LDA_A + xf * 8])     = __ldg(reinterpret_cast<const float4*>(xp));
        *reinterpret_cast<float4*>(&A[xr * LDA_A + xf * 8 + 4]) = __ldg(reinterpret_cast<const float4*>(xp + 4));
    }
    __syncthreads();

    #pragma unroll 1
    for (int s = 0; s < NS; ++s) {
        u64 acc[8][2];
        #pragma unroll
        for (int i = 0; i < 8; ++i) { acc[i][0] = 0; acc[i][1] = 0; }
        wgemmN<2>(A, LDA_A, NOBS + NENC, Wi2h, NENC, col1, rg, acc);

        // prefetch next step's x while waiting at the barrier
        float4 x0, x1;
        if (s + 1 < NS) {
            const float* xp = &obs[((size_t)(m0 + xr) * NS + (NS - 2 - s)) * NOBS + xf * 8];
            x0 = __ldg(reinterpret_cast<const float4*>(xp));
            x1 = __ldg(reinterpret_cast<const float4*>(xp + 4));
        }
        __syncthreads();   // all A reads done

        #pragma unroll
        for (int i = 0; i < 8; ++i) {
            int row = rg + 8 * i;
            float c0, c1, c2, c3;
            upk2(c0, c1, acc[i][0]); upk2(c2, c3, acc[i][1]);
            *reinterpret_cast<float4*>(&A[row * LDA_A + NOBS + col1]) =
                make_float4(tanhf(c0 + bi.x), tanhf(c1 + bi.y),
                            tanhf(c2 + bi.z), tanhf(c3 + bi.w));
        }
        if (s + 1 < NS) {
            *reinterpret_cast<float4*>(&A[xr * LDA_A + xf * 8])     = x0;
            *reinterpret_cast<float4*>(&A[xr * LDA_A + xf * 8 + 4]) = x1;
        }
        __syncthreads();
    }

    // head: O = h @ Wh2o + b   (written into A cols 0..255 after reads complete)
    u64 acc[8][2];
    #pragma unroll
    for (int i = 0; i < 8; ++i) { acc[i][0] = 0; acc[i][1] = 0; }
    wgemmN<2>(A + NOBS, LDA_A, NENC, Wh2o, 2 * NLAT, col1, rg, acc);
    float4 bh = __ldg(reinterpret_cast<const float4*>(&bh2o[col1]));
    __syncthreads();
    #pragma unroll
    for (int i = 0; i < 8; ++i) {
        int row = rg + 8 * i;
        float c0, c1, c2, c3;
        upk2(c0, c1, acc[i][0]); upk2(c2, c3, acc[i][1]);
        *reinterpret_cast<float4*>(&A[row * LDA_A + col1]) =
            make_float4(c0 + bh.x, c1 + bh.y, c2 + bh.z, c3 + bh.w);
    }
    __syncthreads();

    // z0 = mean + eps * exp(0.5*logvar); emit mean/logvar
    const size_t MEAN_OFF = (size_t)NT * NB * NOBS;
    const size_t LV_OFF   = MEAN_OFF + (size_t)NB * NLAT;
    int col2 = w * 8 + cg * 2;
    #pragma unroll
    for (int i = 0; i < 8; ++i) {
        int row = rg + 8 * i, m = m0 + row;
        float2 mv = *reinterpret_cast<const float2*>(&A[row * LDA_A + col2]);
        float2 lv = *reinterpret_cast<const float2*>(&A[row * LDA_A + NLAT + col2]);
        float2 ev = __ldg(reinterpret_cast<const float2*>(&eps[(size_t)m * NLAT + col2]));
        float2 z;
        z.x = mv.x + ev.x * expf(0.5f * lv.x);
        z.y = mv.y + ev.y * expf(0.5f * lv.y);
        *reinterpret_cast<float2*>(&g_z0[(size_t)m * NLAT + col2]) = z;
        *reinterpret_cast<float2*>(&out[MEAN_OFF + (size_t)m * NLAT + col2]) = mv;
        *reinterpret_cast<float2*>(&out[LV_OFF   + (size_t)m * NLAT + col2]) = lv;
    }
}

// ==================== Persistent ODE: 63x4 RK4 substeps + 64 decodes ====================
__global__ void __launch_bounds__(NTHREADS)
ode_kernel(const float* __restrict__ W1,  const float* __restrict__ b1,
           const float* __restrict__ W2,  const float* __restrict__ b2,
           const float* __restrict__ Wd1, const float* __restrict__ bd1,
           const float* __restrict__ Wd2, const float* __restrict__ bd2,
           const float* __restrict__ ptimes, float* __restrict__ out)
{
    extern __shared__ float sm[];
    float* Z  = sm;                            // [64][132] stage input zc
    float* G  = sm + TM * LDA_Z;               // [64][260] hidden activations
    float* ZB = sm + TM * LDA_Z + TM * LDA_G;  // [64][128] substep base z
    int tid = threadIdx.x, lane = tid & 31, w = tid >> 5;
    int rg = lane >> 2, cg = lane & 3;
    int m0 = blockIdx.x * TM;
    int col1 = w * 16 + cg * 4;   // 256-col GEMMs
    int col2 = w * 8  + cg * 2;   // 128-col GEMM (z)
    int colD = w * 4  + cg;       // 64-col decode output

    float4 b1v  = __ldg(reinterpret_cast<const float4*>(&b1[col1]));
    float4 bd1v = __ldg(reinterpret_cast<const float4*>(&bd1[col1]));
    float2 b2v  = __ldg(reinterpret_cast<const float2*>(&b2[col2]));
    float  bd2v = __ldg(&bd2[colD]);

    // current z: this thread owns rows {rg+8i} x cols {col2, col2+1}
    float zr[8][2];
    #pragma unroll
    for (int i = 0; i < 8; ++i) {
        int row = rg + 8 * i;
        float2 v = *reinterpret_cast<const float2*>(&g_z0[(size_t)(m0 + row) * NLAT + col2]);
        zr[i][0] = v.x; zr[i][1] = v.y;
        *reinterpret_cast<float2*>(&Z[row * LDA_Z + col2]) = v;
    }
    __syncthreads();

    auto decode = [&](int tindex) {
        u64 a1[8][2];
        #pragma unroll
        for (int i = 0; i < 8; ++i) { a1[i][0] = 0; a1[i][1] = 0; }
        wgemmN<2>(Z, LDA_Z, NLAT, Wd1, NDEC, col1, rg, a1);
        #pragma unroll
        for (int i = 0; i < 8; ++i) {
            int row = rg + 8 * i;
            float c0, c1, c2, c3;
            upk2(c0, c1, a1[i][0]); upk2(c2, c3, a1[i][1]);
            *reinterpret_cast<float4*>(&G[row * LDA_G + col1]) =
                make_float4(fmaxf(c0 + bd1v.x, 0.f), fmaxf(c1 + bd1v.y, 0.f),
                            fmaxf(c2 + bd1v.z, 0.f), fmaxf(c3 + bd1v.w, 0.f));
        }
        __syncthreads();
        float a2[8];
        #pragma unroll
        for (int i = 0; i < 8; ++i) a2[i] = 0.f;
        wgemmS(G, LDA_G, NDEC, Wd2, NOBS, colD, rg, a2);
        #pragma unroll
        for (int i = 0; i < 8; ++i) {
            int row = rg + 8 * i;
            out[((size_t)tindex * NB + (m0 + row)) * NOBS + colD] = a2[i] + bd2v;
        }
        __syncthreads();   // G reads done before next stage overwrites G
    };

    decode(0);

    #pragma unroll 1
    for (int iv = 0; iv < NT - 1; ++iv) {
        float dt = (__ldg(&ptimes[iv + 1]) - __ldg(&ptimes[iv])) * (1.0f / NSUB);
        #pragma unroll 1
        for (int ss = 0; ss < NSUB; ++ss) {
            // stash substep base z (thread-private cells: no barrier needed)
            #pragma unroll
            for (int i = 0; i < 8; ++i)
                *reinterpret_cast<float2*>(&ZB[(rg + 8 * i) * NLAT + col2]) =
                    make_float2(zr[i][0], zr[i][1]);

            #pragma unroll 1
            for (int s = 0; s < 4; ++s) {
                float wt = (s == 0 || s == 3) ? dt * (1.0f / 6.0f) : dt * (1.0f / 3.0f);
                float ci = (s == 2) ? dt : 0.5f * dt;

                // g = tanh(zc @ W1 + b1)
                u64 a1[8][2];
                #pragma unroll
                for (int i = 0; i < 8; ++i) { a1[i][0] = 0; a1[i][1] = 0; }
                wgemmN<2>(Z, LDA_Z, NLAT, W1, NODE, col1, rg, a1);
                #pragma unroll
                for (int i = 0; i < 8; ++i) {
                    int row = rg + 8 * i;
                    float c0, c1, c2, c3;
                    upk2(c0, c1, a1[i][0]); upk2(c2, c3, a1[i][1]);
                    *reinterpret_cast<float4*>(&G[row * LDA_G + col1]) =
                        make_float4(tanhf(c0 + b1v.x), tanhf(c1 + b1v.y),
                                    tanhf(c2 + b1v.z), tanhf(c3 + b1v.w));
                }
                __syncthreads();   // all GEMM1 (Z reads) + G writes complete

                // k = g @ W2 + b2 ; fold into RK4 accumulator and next stage input
                u64 a2[8][1];
                #pragma unroll
                for (int i = 0; i < 8; ++i) a2[i][0] = 0;
                wgemmN<1>(G, LDA_G, NODE, W2, NLAT, col2, rg, a2);
                #pragma unroll
                for (int i = 0; i < 8; ++i) {
                    int row = rg + 8 * i;
                    float k0, k1;
                    upk2(k0, k1, a2[i][0]);
                    k0 += b2v.x; k1 += b2v.y;
                    zr[i][0] += wt * k0; zr[i][1] += wt * k1;
                    float2 v;
                    if (s < 3) {
                        float2 zb = *reinterpret_cast<const float2*>(&ZB[row * NLAT + col2]);
                        v = make_float2(zb.x + ci * k0, zb.y + ci * k1);
                    } else {
                        v = make_float2(zr[i][0], zr[i][1]);
                    }
                    *reinterpret_cast<float2*>(&Z[row * LDA_Z + col2]) = v;
                }
                __syncthreads();   // Z consistent before next GEMM1 / decode
            }
        }
        decode(iv + 1);
    }
}

// -------------------- Launcher --------------------
extern "C" void kernel_launch(void* const* d_in, const int* in_sizes, int n_in,
                              void* d_out, int out_size)
{
    const float* obs    = (const float*)d_in[0];
    /* d_in[1] observed_times: unused by the reference computation */
    const float* ptimes = (const float*)d_in[2];
    const float* eps    = (const float*)d_in[3];
    const float* Wi2h   = (const float*)d_in[4];
    const float* bi2h   = (const float*)d_in[5];
    const float* Wh2o   = (const float*)d_in[6];
    const float* bh2o   = (const float*)d_in[7];
    const float* Wode1  = (const float*)d_in[8];
    const float* bode1  = (const float*)d_in[9];
    const float* Wode2  = (const float*)d_in[10];
    const float* bode2  = (const float*)d_in[11];
    const float* Wdec1  = (const float*)d_in[12];
    const float* bdec1  = (const float*)d_in[13];
    const float* Wdec2  = (const float*)d_in[14];
    const float* bdec2  = (const float*)d_in[15];
    float* out = (float*)d_out;

    const int SM_ENC = TM * LDA_A * 4;                              // 82944
    const int SM_ODE = (TM * LDA_Z + TM * LDA_G + TM * NLAT) * 4;   // 133120

    cudaFuncSetAttribute(encoder_kernel, cudaFuncAttributeMaxDynamicSharedMemorySize, SM_ENC);
    cudaFuncSetAttribute(ode_kernel,     cudaFuncAttributeMaxDynamicSharedMemorySize, SM_ODE);

    dim3 grid(NB / TM);   // 128 CTAs

    encoder_kernel<<<grid, NTHREADS, SM_ENC>>>(obs, Wi2h, bi2h, Wh2o, bh2o, eps, out);
    ode_kernel<<<grid, NTHREADS, SM_ODE>>>(Wode1, bode1, Wode2, bode2,
                                           Wdec1, bdec1, Wdec2, bdec2, ptimes, out);
}